// round 2
// baseline (speedup 1.0000x reference)
#include <cuda_runtime.h>
#include <cstdint>

// CTC forward loss, one CTA per batch element.
// B=256, T=512, C=128, L=64, S=2L+1=129, blank=C-1=127.
// Recurrence: alpha_t[s] = logaddexp3(alpha_{t-1}[s], alpha_{t-1}[s-1],
//                                     skip[s] ? alpha_{t-1}[s-2] : NEG) + logp[t, lab_ext[s]]
// y_pred rows (512B) prefetched D steps ahead via cp.async into a shared ring.

#define CTC_B 256
#define CTC_T 512
#define CTC_C 128
#define CTC_L 64
#define CTC_S (2 * CTC_L + 1)   // 129
#define BLANK (CTC_C - 1)       // 127
#define DEPTH 8                 // cp.async ring depth (rows in flight)
#define NTHREADS 160            // 5 warps: 129 state threads + loaders

#define NEGINF (-1e30f)
#define EPS_F  (1e-7f)

__device__ __forceinline__ void cp_async16(void* smem_dst, const void* gmem_src) {
    unsigned saddr = (unsigned)__cvta_generic_to_shared(smem_dst);
    asm volatile("cp.async.cg.shared.global [%0], [%1], 16;\n"
                 :: "r"(saddr), "l"(gmem_src) : "memory");
}
#define CP_COMMIT() asm volatile("cp.async.commit_group;\n" ::: "memory")
#define CP_WAIT(n)  asm volatile("cp.async.wait_group %0;\n" :: "n"(n) : "memory")

__global__ __launch_bounds__(NTHREADS, 2)
void ctc_loss_kernel(const float* __restrict__ y_pred,      // [B, T, C]
                     const int*   __restrict__ labels,      // [B, L]
                     const int*   __restrict__ input_length,// [B, 1]
                     const int*   __restrict__ label_length,// [B, 1]
                     float*       __restrict__ out)         // [B, 1]
{
    __shared__ float rows[DEPTH][CTC_C];       // raw y_pred rows (prob domain)
    __shared__ float alpha[2][CTC_S + 2];      // +2 left pad of NEG
    __shared__ float pairv[2];                 // {alpha[s_end], alpha[s_end-1]} at t_idx

    const int b   = blockIdx.x;
    const int tid = threadIdx.x;
    const float* yb = y_pred + (size_t)b * CTC_T * CTC_C;

    // ---- per-thread static state: extended label + skip flag ----
    const int s = tid;                 // state index if tid < S
    int  lab  = BLANK;
    bool skip = false;
    if (tid < CTC_S) {
        if (s & 1) {
            lab = labels[b * CTC_L + (s >> 1)];
            if (s >= 3)
                skip = (lab != labels[b * CTC_L + (s >> 1) - 1]);
        }
    }
    const int t_idx = input_length[b] - 1;
    const int s_end = 2 * label_length[b];

    // NEG padding for alpha left edge (both buffers)
    if (tid < 2) {
        alpha[0][tid] = NEGINF;
        alpha[1][tid] = NEGINF;
    }

    // ---- prologue: issue rows 0..DEPTH-2 (DEPTH-1 commit groups) ----
    #pragma unroll
    for (int r = 0; r < DEPTH - 1; ++r) {
        if (r < CTC_T && tid < 32)
            cp_async16(&rows[r][tid * 4], yb + (size_t)r * CTC_C + tid * 4);
        CP_COMMIT();
    }

    // ---- main serial loop over time ----
    for (int t = 0; t < CTC_T; ++t) {
        // row t is the oldest of (DEPTH-1) pending groups -> done when <= DEPTH-2 pend
        CP_WAIT(DEPTH - 2);
        __syncthreads();   // row t visible to all; alpha buffers & old row slot free

        // issue row t+DEPTH-1 into slot (t-1)%DEPTH (consumed at step t-1, freed by the sync)
        const int nt = t + DEPTH - 1;
        if (nt < CTC_T && tid < 32)
            cp_async16(&rows[nt % DEPTH][tid * 4], yb + (size_t)nt * CTC_C + tid * 4);
        CP_COMMIT();

        const float* __restrict__ row   = rows[t % DEPTH];
        float*       __restrict__ acur  = alpha[t & 1] + 2;
        const float* __restrict__ aprev = alpha[(t + 1) & 1] + 2;

        if (tid < CTC_S) {
            const float lp = __logf(row[lab] + EPS_F);
            float na;
            if (t == 0) {
                na = (s < 2) ? lp : NEGINF;
            } else {
                const float a1 = aprev[s];
                const float a2 = aprev[s - 1];
                const float a3 = skip ? aprev[s - 2] : NEGINF;
                const float m  = fmaxf(a1, fmaxf(a2, a3));
                na = m + __logf(__expf(a1 - m) + __expf(a2 - m) + __expf(a3 - m)) + lp;
            }
            acur[s] = na;
            if (t == t_idx) {
                if (s == s_end)     pairv[0] = na;
                if (s == s_end - 1) pairv[1] = na;
            }
        }
    }

    __syncthreads();
    if (tid == 0) {
        const float a = pairv[0];
        const float c = pairv[1];
        const float m = fmaxf(a, c);
        out[b] = -(m + __logf(__expf(a - m) + __expf(c - m)));
    }
}

extern "C" void kernel_launch(void* const* d_in, const int* in_sizes, int n_in,
                              void* d_out, int out_size) {
    const float* y_pred       = (const float*)d_in[0];
    const int*   labels       = (const int*)  d_in[1];
    const int*   input_length = (const int*)  d_in[2];
    const int*   label_length = (const int*)  d_in[3];
    float*       out          = (float*)d_out;

    ctc_loss_kernel<<<CTC_B, NTHREADS>>>(y_pred, labels, input_length, label_length, out);
}